// round 2
// baseline (speedup 1.0000x reference)
#include <cuda_runtime.h>
#include <math_constants.h>

#define D   256
#define K   1024
#define TM  64          // rows per block
#define TNT 256         // codes per tile
#define NTILES (K/TNT)  // 4
#define KC  32          // d-chunk

#define ZT_STRIDE 68    // padded stride for zt[d][row]  (bank-conflict avoidance, 16B-aligned rows)
#define CT_STRIDE 260   // padded stride for ct[d][code]

__device__ float  g_cnorm[K];
__device__ int    g_idx[65536];
__device__ double g_loss_sum;

// ---- packed f32x2 helpers (FFMA2 only reachable via PTX) ----
__device__ __forceinline__ unsigned long long pack2(float x, float y){
    unsigned long long r;
    asm("mov.b64 %0, {%1, %2};" : "=l"(r) : "f"(x), "f"(y));
    return r;
}
__device__ __forceinline__ void unpack2(unsigned long long v, float& x, float& y){
    asm("mov.b64 {%0, %1}, %2;" : "=f"(x), "=f"(y) : "l"(v));
}
__device__ __forceinline__ unsigned long long ffma2(unsigned long long a,
                                                    unsigned long long b,
                                                    unsigned long long c){
    unsigned long long d_;
    asm("fma.rn.f32x2 %0, %1, %2, %3;" : "=l"(d_) : "l"(a), "l"(b), "l"(c));
    return d_;
}

// ---------------------------------------------------------------------------
// Kernel 1: codebook squared norms + zero the loss accumulator
// grid = K/8 blocks of 256 (8 warps, one code per warp)
// ---------------------------------------------------------------------------
__global__ void k_setup(const float* __restrict__ cb){
    if (blockIdx.x == 0 && threadIdx.x == 0) g_loss_sum = 0.0;
    int w    = threadIdx.x >> 5;
    int lane = threadIdx.x & 31;
    int code = blockIdx.x * 8 + w;
    const float* c = cb + (size_t)code * D;
    float s = 0.f;
    #pragma unroll
    for (int j = 0; j < 8; j++){
        float v = c[lane + 32 * j];
        s = __fmaf_rn(v, v, s);
    }
    #pragma unroll
    for (int off = 16; off; off >>= 1)
        s += __shfl_xor_sync(0xffffffffu, s, off);
    if (lane == 0) g_cnorm[code] = s;
}

// ---------------------------------------------------------------------------
// Kernel 2: fused distance + argmin.
// Block: 256 threads (tx = tid&31 over codes, ty = tid>>5 over rows).
// Each block owns TM=64 rows, iterates all K codes in NTILES tiles of 256.
// Per-thread register tile: 8 rows x 8 codes, codes packed as f32x2 pairs.
// Score is computed EXACTLY as the reference:  fl( fl(znorm+cnorm) - 2*dot ).
// Tie-break: first (lowest) code index, matching jnp.argmin.
// ---------------------------------------------------------------------------
__global__ __launch_bounds__(256, 2) void k_argmin(
    const float* __restrict__ Z, const float* __restrict__ CB,
    float* __restrict__ out_idx)
{
    extern __shared__ float sm[];
    float* zt = sm;                         // [D][ZT_STRIDE] transposed z tile
    float* ct = zt + D * ZT_STRIDE;         // [KC][CT_STRIDE] transposed code chunk
    float* cn = ct + KC * CT_STRIDE;        // [TNT] cnorm tile
    float* zn = cn + TNT;                   // [TM] z norms
    float* rs = ct;                         // alias (final reduce scores) [TM][32]
    int*   ri = (int*)(ct + TM * 32);       // alias (final reduce indices)

    const int tid  = threadIdx.x;
    const int tx   = tid & 31;
    const int ty   = tid >> 5;
    const int row0 = blockIdx.x * TM;

    // --- load full z tile (64 rows x 256) transposed into smem ---
    {
        const float4* Z4 = (const float4*)(Z + (size_t)row0 * D);
        #pragma unroll
        for (int k = 0; k < 16; k++){
            int idx = tid + k * 256;
            int r   = idx >> 6;       // row 0..63
            int g   = idx & 63;       // float4 within row
            float4 v = Z4[r * 64 + g];
            int d0 = g * 4;
            zt[(d0 + 0) * ZT_STRIDE + r] = v.x;
            zt[(d0 + 1) * ZT_STRIDE + r] = v.y;
            zt[(d0 + 2) * ZT_STRIDE + r] = v.z;
            zt[(d0 + 3) * ZT_STRIDE + r] = v.w;
        }
    }
    __syncthreads();

    // --- znorm per row: LLVM-style 8 strided accumulators + pairwise-halving tree,
    //     no FMA contraction (mimic jnp.sum(z**2) on CPU) ---
    if (tid < TM){
        const float* zr = Z + (size_t)(row0 + tid) * D;
        float a0=0.f,a1=0.f,a2=0.f,a3=0.f,a4=0.f,a5=0.f,a6=0.f,a7=0.f;
        for (int i = 0; i < D; i += 8){
            a0 = __fadd_rn(a0, __fmul_rn(zr[i+0], zr[i+0]));
            a1 = __fadd_rn(a1, __fmul_rn(zr[i+1], zr[i+1]));
            a2 = __fadd_rn(a2, __fmul_rn(zr[i+2], zr[i+2]));
            a3 = __fadd_rn(a3, __fmul_rn(zr[i+3], zr[i+3]));
            a4 = __fadd_rn(a4, __fmul_rn(zr[i+4], zr[i+4]));
            a5 = __fadd_rn(a5, __fmul_rn(zr[i+5], zr[i+5]));
            a6 = __fadd_rn(a6, __fmul_rn(zr[i+6], zr[i+6]));
            a7 = __fadd_rn(a7, __fmul_rn(zr[i+7], zr[i+7]));
        }
        float b0 = __fadd_rn(a0, a4), b1 = __fadd_rn(a1, a5);
        float b2 = __fadd_rn(a2, a6), b3 = __fadd_rn(a3, a7);
        zn[tid] = __fadd_rn(__fadd_rn(b0, b2), __fadd_rn(b1, b3));
    }

    float best_s[8];
    int   best_i[8];
    #pragma unroll
    for (int r = 0; r < 8; r++){ best_s[r] = CUDART_INF_F; best_i[r] = 0; }

    const float4* CB4 = (const float4*)CB;

    for (int t = 0; t < NTILES; t++){
        const int c0 = t * TNT;
        __syncthreads();                      // cn of previous tile fully consumed
        cn[tid] = g_cnorm[c0 + tid];          // 256 threads load 256 norms

        unsigned long long acc[8][4];
        #pragma unroll
        for (int r = 0; r < 8; r++)
            #pragma unroll
            for (int p = 0; p < 4; p++) acc[r][p] = 0ull;

        for (int d0 = 0; d0 < D; d0 += KC){
            __syncthreads();
            // load code chunk (256 codes x 32 d) transposed
            #pragma unroll
            for (int k = 0; k < 8; k++){
                int idx  = tid + k * 256;
                int code = idx >> 3;         // 0..255
                int g    = idx & 7;          // float4 within chunk
                float4 v = CB4[(size_t)(c0 + code) * 64 + (d0 >> 2) + g];
                int dd = g * 4;
                ct[(dd + 0) * CT_STRIDE + code] = v.x;
                ct[(dd + 1) * CT_STRIDE + code] = v.y;
                ct[(dd + 2) * CT_STRIDE + code] = v.z;
                ct[(dd + 3) * CT_STRIDE + code] = v.w;
            }
            __syncthreads();

            #pragma unroll 8
            for (int kk = 0; kk < KC; kk++){
                const float* ztrow = zt + (d0 + kk) * ZT_STRIDE + ty * 8;
                float4 za = *(const float4*)(ztrow);
                float4 zb = *(const float4*)(ztrow + 4);
                ulonglong2 cA = *(const ulonglong2*)(ct + kk * CT_STRIDE + tx * 4);
                ulonglong2 cB = *(const ulonglong2*)(ct + kk * CT_STRIDE + 128 + tx * 4);
                unsigned long long zp[8];
                zp[0] = pack2(za.x, za.x); zp[1] = pack2(za.y, za.y);
                zp[2] = pack2(za.z, za.z); zp[3] = pack2(za.w, za.w);
                zp[4] = pack2(zb.x, zb.x); zp[5] = pack2(zb.y, zb.y);
                zp[6] = pack2(zb.z, zb.z); zp[7] = pack2(zb.w, zb.w);
                #pragma unroll
                for (int r = 0; r < 8; r++){
                    acc[r][0] = ffma2(zp[r], cA.x, acc[r][0]);
                    acc[r][1] = ffma2(zp[r], cA.y, acc[r][1]);
                    acc[r][2] = ffma2(zp[r], cB.x, acc[r][2]);
                    acc[r][3] = ffma2(zp[r], cB.y, acc[r][3]);
                }
            }
        }

        // epilogue: score = fl( fl(zn + cn) - 2*dot ); 2*dot is exact so fmaf(-2,dot,t)
        // is the same single-rounded value the reference produces.
        #pragma unroll
        for (int r = 0; r < 8; r++){
            float zn_r = zn[ty * 8 + r];
            #pragma unroll
            for (int p = 0; p < 4; p++){
                float dlo, dhi;
                unpack2(acc[r][p], dlo, dhi);
                int clocal = (p < 2) ? (tx * 4 + p * 2) : (128 + tx * 4 + (p - 2) * 2);
                float t1 = __fadd_rn(zn_r, cn[clocal]);
                float s1 = __fmaf_rn(-2.0f, dlo, t1);
                if (s1 < best_s[r]) { best_s[r] = s1; best_i[r] = c0 + clocal; }
                float t2 = __fadd_rn(zn_r, cn[clocal + 1]);
                float s2 = __fmaf_rn(-2.0f, dhi, t2);
                if (s2 < best_s[r]) { best_s[r] = s2; best_i[r] = c0 + clocal + 1; }
            }
        }
    }

    // --- cross-thread (tx) reduce per row with lexicographic (score, index) min ---
    __syncthreads();
    #pragma unroll
    for (int r = 0; r < 8; r++){
        rs[(ty * 8 + r) * 32 + tx] = best_s[r];
        ri[(ty * 8 + r) * 32 + tx] = best_i[r];
    }
    __syncthreads();
    if (tid < TM){
        float bs = CUDART_INF_F;
        int   bi = K;
        #pragma unroll
        for (int x = 0; x < 32; x++){
            float s = rs[tid * 32 + x];
            int   i = ri[tid * 32 + x];
            if (s < bs || (s == bs && i < bi)){ bs = s; bi = i; }
        }
        g_idx[row0 + tid]  = bi;
        out_idx[row0 + tid] = (float)bi;
    }
}

// ---------------------------------------------------------------------------
// Kernel 3: gather z_q, write straight-through output exactly as the reference
// (z_e + fl(z_q - z_e)), and accumulate sum of squared diffs for the loss.
// ---------------------------------------------------------------------------
__global__ void k_gather(const float4* __restrict__ Z4,
                         const float4* __restrict__ CB4,
                         float4* __restrict__ O4)
{
    __shared__ float wsum[8];
    int e   = blockIdx.x * blockDim.x + threadIdx.x;  // float4 index
    int row = e >> 6;                                  // 64 float4 per row
    int c   = e & 63;
    int idx = g_idx[row];
    float4 z = Z4[e];
    float4 q = CB4[(size_t)idx * 64 + c];

    float d0 = __fsub_rn(q.x, z.x);
    float d1 = __fsub_rn(q.y, z.y);
    float d2 = __fsub_rn(q.z, z.z);
    float d3 = __fsub_rn(q.w, z.w);

    float4 o;
    o.x = __fadd_rn(z.x, d0);
    o.y = __fadd_rn(z.y, d1);
    o.z = __fadd_rn(z.z, d2);
    o.w = __fadd_rn(z.w, d3);
    O4[e] = o;

    float s = d0 * d0 + d1 * d1 + d2 * d2 + d3 * d3;
    #pragma unroll
    for (int off = 16; off; off >>= 1)
        s += __shfl_xor_sync(0xffffffffu, s, off);
    int lane = threadIdx.x & 31, w = threadIdx.x >> 5;
    if (lane == 0) wsum[w] = s;
    __syncthreads();
    if (threadIdx.x == 0){
        float bsum = 0.f;
        #pragma unroll
        for (int i = 0; i < 8; i++) bsum += wsum[i];
        atomicAdd(&g_loss_sum, (double)bsum);
    }
}

// ---------------------------------------------------------------------------
// Kernel 4: finalize loss:  vq = mean + 0.25*mean
// ---------------------------------------------------------------------------
__global__ void k_loss(float* __restrict__ out_loss, int n_total){
    double m  = g_loss_sum / (double)n_total;
    float  cb = (float)m;
    out_loss[0] = __fadd_rn(cb, __fmul_rn(0.25f, cb));
}

// ---------------------------------------------------------------------------
extern "C" void kernel_launch(void* const* d_in, const int* in_sizes, int n_in,
                              void* d_out, int out_size)
{
    const float* Z  = (const float*)d_in[0];
    const float* CB = (const float*)d_in[1];
    float* out = (float*)d_out;
    const int n_z = in_sizes[0];      // 16777216
    const int N   = n_z >> 8;         // 65536 rows

    k_setup<<<K / 8, 256>>>(CB);

    const int smem = (D * ZT_STRIDE + KC * CT_STRIDE + TNT + TM) * (int)sizeof(float);
    cudaFuncSetAttribute(k_argmin, cudaFuncAttributeMaxDynamicSharedMemorySize, smem);
    // out layout: [ z_q_st (n_z) | vq_loss (1) | indices (N) ]
    k_argmin<<<N / TM, 256, smem>>>(Z, CB, out + n_z + 1);

    k_gather<<<(n_z / 4) / 256, 256>>>((const float4*)Z, (const float4*)CB, (float4*)out);

    k_loss<<<1, 1>>>(out + n_z, n_z);
}

// round 4
// speedup vs baseline: 1.9216x; 1.9216x over previous
#include <cuda_runtime.h>
#include <cuda_bf16.h>
#include <cuda_fp16.h>
#include <math_constants.h>

#define D     256
#define K     1024
#define NROWS 65536
#define GM    64            // rows per gemm block
#define CAP   16
#define MARGIN 3.0e-3f
#define SCSTR 1032          // score smem stride (halfs)

__device__ float  g_cnorm[K];
__device__ int    g_idx[NROWS];
__device__ double g_loss_sum;
__device__ __nv_bfloat16 g_zbf[NROWS * D];   // 32 MB
__device__ __nv_bfloat16 g_cbf[K * D];       // 512 KB
__device__ unsigned short g_cand[NROWS * CAP];
__device__ int    g_ccnt[NROWS];

// ---------------------------------------------------------------------------
__device__ __forceinline__ void mma16816(float* c, const unsigned* a,
                                         unsigned b0, unsigned b1){
    asm volatile("mma.sync.aligned.m16n8k16.row.col.f32.bf16.bf16.f32 "
        "{%0,%1,%2,%3}, {%4,%5,%6,%7}, {%8,%9}, {%0,%1,%2,%3};"
        : "+f"(c[0]), "+f"(c[1]), "+f"(c[2]), "+f"(c[3])
        : "r"(a[0]), "r"(a[1]), "r"(a[2]), "r"(a[3]), "r"(b0), "r"(b1));
}

// ---------------------------------------------------------------------------
// Kernel 0: z f32 -> bf16
// ---------------------------------------------------------------------------
__global__ void k_zconv(const float4* __restrict__ Z4){
    int idx = blockIdx.x * blockDim.x + threadIdx.x;   // 0..1048575
    uint4* dst = (uint4*)g_zbf;
    #pragma unroll
    for (int j = 0; j < 2; j++){
        float4 x = Z4[idx * 4 + j * 2];
        float4 y = Z4[idx * 4 + j * 2 + 1];
        __nv_bfloat162 p0 = __floats2bfloat162_rn(x.x, x.y);
        __nv_bfloat162 p1 = __floats2bfloat162_rn(x.z, x.w);
        __nv_bfloat162 p2 = __floats2bfloat162_rn(y.x, y.y);
        __nv_bfloat162 p3 = __floats2bfloat162_rn(y.z, y.w);
        uint4 o;
        o.x = *(unsigned*)&p0; o.y = *(unsigned*)&p1;
        o.z = *(unsigned*)&p2; o.w = *(unsigned*)&p3;
        dst[idx * 2 + j] = o;
    }
}

// ---------------------------------------------------------------------------
// Kernel 1: codebook norms (bit-exact path from round 0) + cb->bf16 + zero loss
// grid 128 x 256
// ---------------------------------------------------------------------------
__global__ void k_setup(const float* __restrict__ cb){
    if (blockIdx.x == 0 && threadIdx.x == 0) g_loss_sum = 0.0;
    int w    = threadIdx.x >> 5;
    int lane = threadIdx.x & 31;
    int code = blockIdx.x * 8 + w;
    const float* c = cb + (size_t)code * D;
    float s = 0.f;
    #pragma unroll
    for (int j = 0; j < 8; j++){
        float v = c[lane + 32 * j];
        s = __fmaf_rn(v, v, s);
    }
    #pragma unroll
    for (int off = 16; off; off >>= 1)
        s += __shfl_xor_sync(0xffffffffu, s, off);
    if (lane == 0) g_cnorm[code] = s;

    // bf16 conversion: 32768 threads x 1 uint4 (8 halfs)
    int g = blockIdx.x * 256 + threadIdx.x;
    const float4* cb4 = (const float4*)cb;
    float4 x = cb4[g * 2], y = cb4[g * 2 + 1];
    __nv_bfloat162 p0 = __floats2bfloat162_rn(x.x, x.y);
    __nv_bfloat162 p1 = __floats2bfloat162_rn(x.z, x.w);
    __nv_bfloat162 p2 = __floats2bfloat162_rn(y.x, y.y);
    __nv_bfloat162 p3 = __floats2bfloat162_rn(y.z, y.w);
    uint4 o;
    o.x = *(unsigned*)&p0; o.y = *(unsigned*)&p1;
    o.z = *(unsigned*)&p2; o.w = *(unsigned*)&p3;
    ((uint4*)g_cbf)[g] = o;
}

// ---------------------------------------------------------------------------
// Kernel 2: bf16 HMMA approx scores + per-row min scan + candidate emission.
// Block = 256 threads (8 warps), 64 rows, all 1024 codes.
// Warp tile: 32 rows x 64 codes, m16n8k16 mma.
// smem: scores f16 [64][1032] | A bf16 [64][264] | B bf16 [256][72]
//       | cn f32 [1024] | cand u16 [64*16] | cnt i32 [64]
// ---------------------------------------------------------------------------
__global__ __launch_bounds__(256, 1) void k_gemm(){
    extern __shared__ __align__(16) unsigned char smraw[];
    __half*         sc    = (__half*)smraw;                          // 132096 B
    __nv_bfloat16*  sa    = (__nv_bfloat16*)(smraw + 132096);        //  33792 B
    __nv_bfloat16*  sb    = (__nv_bfloat16*)(smraw + 132096 + 33792);//  36864 B
    float*          cns   = (float*)(smraw + 202752);                //   4096 B
    unsigned short* candb = (unsigned short*)(smraw + 206848);       //   2048 B
    int*            cntb  = (int*)(smraw + 208896);                  //    256 B

    const int tid  = threadIdx.x;
    const int lane = tid & 31;
    const int w    = tid >> 5;
    const int gid  = lane >> 2;
    const int tig  = lane & 3;
    const int wm   = w >> 2;          // 0..1 -> row group
    const int wn   = w & 3;           // 0..3 -> code group
    const int row0 = blockIdx.x * GM;

    // --- load A tile (64 x 256 bf16) into padded smem ---
    const int4* zb4 = (const int4*)g_zbf;
    #pragma unroll
    for (int j = 0; j < 8; j++){
        int i  = tid + 256 * j;
        int r  = i >> 5, c8 = i & 31;
        int4 v = zb4[(size_t)(row0 + r) * 32 + c8];
        *(int4*)(sa + r * 264 + c8 * 8) = v;
    }
    #pragma unroll
    for (int j = 0; j < 4; j++) cns[tid + 256 * j] = g_cnorm[tid + 256 * j];
    if (tid < GM) cntb[tid] = 0;
    __syncthreads();

    const int4* cb4 = (const int4*)g_cbf;
    for (int ct = 0; ct < 4; ct++){
        float acc[2][8][4];
        #pragma unroll
        for (int m = 0; m < 2; m++)
            #pragma unroll
            for (int n = 0; n < 8; n++)
                #pragma unroll
                for (int q = 0; q < 4; q++) acc[m][n][q] = 0.f;

        for (int kc = 0; kc < 4; kc++){
            __syncthreads();
            // load B chunk: 256 codes x 64 halfs
            #pragma unroll
            for (int j = 0; j < 8; j++){
                int i    = tid + 256 * j;
                int code = i >> 3, c8 = i & 7;
                int4 v = cb4[(size_t)(ct * 256 + code) * 32 + kc * 8 + c8];
                *(int4*)(sb + code * 72 + c8 * 8) = v;
            }
            __syncthreads();

            #pragma unroll
            for (int ks = 0; ks < 4; ks++){
                int kb = kc * 64 + ks * 16;
                unsigned a[2][4];
                #pragma unroll
                for (int m = 0; m < 2; m++){
                    int ra = wm * 32 + m * 16 + gid;
                    const __nv_bfloat16* ap = sa + ra * 264 + kb + 2 * tig;
                    a[m][0] = *(const unsigned*)(ap);
                    a[m][1] = *(const unsigned*)(ap + 264 * 8);
                    a[m][2] = *(const unsigned*)(ap + 8);
                    a[m][3] = *(const unsigned*)(ap + 264 * 8 + 8);
                }
                #pragma unroll
                for (int n = 0; n < 8; n++){
                    int cbi = wn * 64 + n * 8 + gid;
                    const __nv_bfloat16* bp = sb + cbi * 72 + ks * 16 + 2 * tig;
                    unsigned b0 = *(const unsigned*)(bp);
                    unsigned b1 = *(const unsigned*)(bp + 8);
                    mma16816(acc[0][n], a[0], b0, b1);
                    mma16816(acc[1][n], a[1], b0, b1);
                }
            }
        }

        // epilogue: approx score = cn - 2*dot, store fp16
        #pragma unroll
        for (int m = 0; m < 2; m++){
            int r0 = wm * 32 + m * 16 + gid;
            #pragma unroll
            for (int n = 0; n < 8; n++){
                int col = ct * 256 + wn * 64 + n * 8 + 2 * tig;
                float c0 = cns[col], c1 = cns[col + 1];
                float s0 = c0 - 2.f * acc[m][n][0];
                float s1 = c1 - 2.f * acc[m][n][1];
                float s2 = c0 - 2.f * acc[m][n][2];
                float s3 = c1 - 2.f * acc[m][n][3];
                *(__half2*)(sc + r0 * SCSTR + col)       = __floats2half2_rn(s0, s1);
                *(__half2*)(sc + (r0 + 8) * SCSTR + col) = __floats2half2_rn(s2, s3);
            }
        }
    }
    __syncthreads();

    // --- per-row min scan + candidate emission (warp w: rows w*8 .. w*8+7) ---
    for (int rr = 0; rr < 8; rr++){
        int r = w * 8 + rr;
        const __half* srow = sc + r * SCSTR;
        float mn = CUDART_INF_F;
        #pragma unroll
        for (int j = 0; j < 32; j++)
            mn = fminf(mn, __half2float(srow[j * 32 + lane]));
        #pragma unroll
        for (int off = 16; off; off >>= 1)
            mn = fminf(mn, __shfl_xor_sync(0xffffffffu, mn, off));
        float thr = mn + MARGIN;
        #pragma unroll
        for (int j = 0; j < 32; j++){
            float vv = __half2float(srow[j * 32 + lane]);
            if (vv <= thr){
                int p = atomicAdd(&cntb[r], 1);
                if (p < CAP) candb[r * CAP + p] = (unsigned short)(j * 32 + lane);
            }
        }
    }
    __syncthreads();
    if (tid < GM) g_ccnt[row0 + tid] = cntb[tid];
    #pragma unroll
    for (int j = 0; j < 4; j++){
        int i = tid + 256 * j;   // 0..1023
        g_cand[(size_t)(row0 + (i >> 4)) * CAP + (i & 15)] = candb[i];
    }
}

// ---------------------------------------------------------------------------
// Kernel 3: exact rescore of candidates. 1 warp per row, bit-exact round-0
// arithmetic: zn via 8-acc pairwise tree, dot via sequential fma, score
// fl(fl(zn+cn)-2dot), tie -> lowest index.
// ---------------------------------------------------------------------------
__global__ __launch_bounds__(256) void k_rescore(
    const float* __restrict__ Z, const float* __restrict__ CB,
    float* __restrict__ out_idx)
{
    __shared__ float szs[8][256];
    __shared__ float scs[8][256];
    const int w    = threadIdx.x >> 5;
    const int lane = threadIdx.x & 31;
    const int row  = blockIdx.x * 8 + w;
    float* zr = szs[w];
    float* cr = scs[w];

    const float4* Z4 = (const float4*)(Z + (size_t)row * D);
    #pragma unroll
    for (int j = 0; j < 2; j++){
        float4 v = Z4[lane + 32 * j];
        *(float4*)(zr + (lane + 32 * j) * 4) = v;
    }
    __syncwarp();

    // zn: exact 8-accumulator pairwise-halving tree
    int l8 = lane & 7;
    float a = 0.f;
    #pragma unroll
    for (int i = 0; i < 32; i++){
        float x = zr[i * 8 + l8];
        a = __fadd_rn(a, __fmul_rn(x, x));
    }
    float aj  = __shfl_sync(0xffffffffu, a, lane & 3);
    float aj4 = __shfl_sync(0xffffffffu, a, (lane & 3) + 4);
    float b   = __fadd_rn(aj, aj4);
    float b0 = __shfl_sync(0xffffffffu, b, 0);
    float b1 = __shfl_sync(0xffffffffu, b, 1);
    float b2 = __shfl_sync(0xffffffffu, b, 2);
    float b3 = __shfl_sync(0xffffffffu, b, 3);
    float zn = __fadd_rn(__fadd_rn(b0, b2), __fadd_rn(b1, b3));

    int cnt   = g_ccnt[row];
    int ncand = (cnt > CAP) ? K : cnt;   // overflow fallback: scan all codes
    float bs = CUDART_INF_F;
    int   bi = K;
    for (int kq = 0; kq < ncand; kq++){
        int ci = (cnt > CAP) ? kq : (int)g_cand[(size_t)row * CAP + kq];
        const float4* C4 = (const float4*)(CB + (size_t)ci * D);
        #pragma unroll
        for (int j = 0; j < 2; j++){
            float4 v = C4[lane + 32 * j];
            *(float4*)(cr + (lane + 32 * j) * 4) = v;
        }
        __syncwarp();
        float t  = __fadd_rn(zn, g_cnorm[ci]);
        float dt = 0.f;
        #pragma unroll 8
        for (int d2 = 0; d2 < D; d2++)
            dt = __fmaf_rn(zr[d2], cr[d2], dt);
        float s = __fmaf_rn(-2.0f, dt, t);
        if (s < bs || (s == bs && ci < bi)){ bs = s; bi = ci; }
        __syncwarp();
    }
    if (lane == 0){
        g_idx[row]   = bi;
        out_idx[row] = (float)bi;
    }
}

// ---------------------------------------------------------------------------
// Kernel 4: gather z_q, straight-through output, loss accumulation (round 0)
// ---------------------------------------------------------------------------
__global__ void k_gather(const float4* __restrict__ Z4,
                         const float4* __restrict__ CB4,
                         float4* __restrict__ O4)
{
    __shared__ float wsum[8];
    int e   = blockIdx.x * blockDim.x + threadIdx.x;
    int row = e >> 6;
    int c   = e & 63;
    int idx = g_idx[row];
    float4 z = Z4[e];
    float4 q = CB4[(size_t)idx * 64 + c];

    float d0 = __fsub_rn(q.x, z.x);
    float d1 = __fsub_rn(q.y, z.y);
    float d2 = __fsub_rn(q.z, z.z);
    float d3 = __fsub_rn(q.w, z.w);

    float4 o;
    o.x = __fadd_rn(z.x, d0);
    o.y = __fadd_rn(z.y, d1);
    o.z = __fadd_rn(z.z, d2);
    o.w = __fadd_rn(z.w, d3);
    O4[e] = o;

    float s = d0 * d0 + d1 * d1 + d2 * d2 + d3 * d3;
    #pragma unroll
    for (int off = 16; off; off >>= 1)
        s += __shfl_xor_sync(0xffffffffu, s, off);
    int lane = threadIdx.x & 31, w = threadIdx.x >> 5;
    if (lane == 0) wsum[w] = s;
    __syncthreads();
    if (threadIdx.x == 0){
        float bsum = 0.f;
        #pragma unroll
        for (int i = 0; i < 8; i++) bsum += wsum[i];
        atomicAdd(&g_loss_sum, (double)bsum);
    }
}

// ---------------------------------------------------------------------------
__global__ void k_loss(float* __restrict__ out_loss, int n_total){
    double m  = g_loss_sum / (double)n_total;
    float  cb = (float)m;
    out_loss[0] = __fadd_rn(cb, __fmul_rn(0.25f, cb));
}

// ---------------------------------------------------------------------------
extern "C" void kernel_launch(void* const* d_in, const int* in_sizes, int n_in,
                              void* d_out, int out_size)
{
    const float* Z  = (const float*)d_in[0];
    const float* CB = (const float*)d_in[1];
    float* out = (float*)d_out;
    const int n_z = in_sizes[0];      // 16777216
    const int N   = n_z >> 8;         // 65536 rows

    k_zconv<<<4096, 256>>>((const float4*)Z);
    k_setup<<<128, 256>>>(CB);

    const int smem = 209152;
    cudaFuncSetAttribute(k_gemm, cudaFuncAttributeMaxDynamicSharedMemorySize, smem);
    k_gemm<<<N / GM, 256, smem>>>();

    // out layout: [ z_q_st (n_z) | vq_loss (1) | indices (N) ]
    k_rescore<<<N / 8, 256>>>(Z, CB, out + n_z + 1);

    k_gather<<<(n_z / 4) / 256, 256>>>((const float4*)Z, (const float4*)CB, (float4*)out);

    k_loss<<<1, 1>>>(out + n_z, n_z);
}

// round 8
// speedup vs baseline: 2.1524x; 1.1201x over previous
#include <cuda_runtime.h>
#include <cuda_bf16.h>
#include <cuda_fp16.h>
#include <math_constants.h>
#include <cstdint>

#define D      256
#define K      1024
#define NROWS  65536
#define GM     128          // rows per gemm block
#define CAP    16
#define MARGIN 3.0e-3f

#define A_STR  264          // halfs, padded
#define B_STR  72           // halfs, padded

__device__ float  g_cnorm[K];
__device__ double g_loss_sum;
__device__ __nv_bfloat16 g_cbf[K * D];       // bf16 codebook
__device__ unsigned short g_cand[NROWS * CAP];
__device__ int    g_ccnt[NROWS];

// ---------------------------------------------------------------------------
__device__ __forceinline__ void mma16816(float* c, const unsigned* a,
                                         unsigned b0, unsigned b1){
    asm volatile("mma.sync.aligned.m16n8k16.row.col.f32.bf16.bf16.f32 "
        "{%0,%1,%2,%3}, {%4,%5,%6,%7}, {%8,%9}, {%0,%1,%2,%3};"
        : "+f"(c[0]), "+f"(c[1]), "+f"(c[2]), "+f"(c[3])
        : "r"(a[0]), "r"(a[1]), "r"(a[2]), "r"(a[3]), "r"(b0), "r"(b1));
}

__device__ __forceinline__ uint32_t s2u(const void* p){
    uint32_t a;
    asm("{ .reg .u64 t; cvta.to.shared.u64 t, %1; cvt.u32.u64 %0, t; }" : "=r"(a) : "l"(p));
    return a;
}

// ---------------------------------------------------------------------------
// Kernel 1: codebook norms (bit-exact) + cb->bf16 + zero loss. grid 128 x 256.
// ---------------------------------------------------------------------------
__global__ void k_setup(const float* __restrict__ cb){
    if (blockIdx.x == 0 && threadIdx.x == 0) g_loss_sum = 0.0;
    int w    = threadIdx.x >> 5;
    int lane = threadIdx.x & 31;
    int code = blockIdx.x * 8 + w;
    const float* c = cb + (size_t)code * D;
    float s = 0.f;
    #pragma unroll
    for (int j = 0; j < 8; j++){
        float v = c[lane + 32 * j];
        s = __fmaf_rn(v, v, s);
    }
    #pragma unroll
    for (int off = 16; off; off >>= 1)
        s += __shfl_xor_sync(0xffffffffu, s, off);
    if (lane == 0) g_cnorm[code] = s;

    int g = blockIdx.x * 256 + threadIdx.x;
    const float4* cb4 = (const float4*)cb;
    float4 x = cb4[g * 2], y = cb4[g * 2 + 1];
    __nv_bfloat162 p0 = __floats2bfloat162_rn(x.x, x.y);
    __nv_bfloat162 p1 = __floats2bfloat162_rn(x.z, x.w);
    __nv_bfloat162 p2 = __floats2bfloat162_rn(y.x, y.y);
    __nv_bfloat162 p3 = __floats2bfloat162_rn(y.z, y.w);
    uint4 o;
    o.x = *(unsigned*)&p0; o.y = *(unsigned*)&p1;
    o.z = *(unsigned*)&p2; o.w = *(unsigned*)&p3;
    ((uint4*)g_cbf)[g] = o;
}

// ---------------------------------------------------------------------------
// Kernel 2: HMMA bf16 GEMM + streaming per-row min / candidate emission.
// 256 threads (8 warps: wm=w>>1 row group of 32, wn=w&1 code group of 64).
// GM=128 rows/block; 8 code tiles of 128; per tile 4 k-chunks of 64 (cp.async
// double-buffered). A (128x256 bf16, converted in-kernel) stays in smem.
// smem ~108 KB -> 2 CTAs/SM.
// ---------------------------------------------------------------------------
__global__ __launch_bounds__(256, 2) void k_gemm(const float* __restrict__ Z){
    extern __shared__ __align__(16) unsigned char smraw[];
    __nv_bfloat16* sa   = (__nv_bfloat16*)smraw;                      // 128*264*2 = 67584
    __nv_bfloat16* sb   = (__nv_bfloat16*)(smraw + 67584);            // 2*128*72*2 = 36864
    float*  cn      = (float*)(smraw + 67584 + 36864);                // 4096
    float*  runmin  = (float*)(smraw + 108544);                       // 512
    float*  tmin    = (float*)(smraw + 109056);                       // 128*2*4 = 1024
    int*    cnt     = (int*)(smraw + 110080);                         // 512
    const uint32_t sb_u = s2u(sb);

    const int tid  = threadIdx.x;
    const int lane = tid & 31;
    const int w    = tid >> 5;
    const int gid  = lane >> 2;
    const int tig  = lane & 3;
    const int wm   = w >> 1;           // 0..3
    const int wn   = w & 1;            // 0..1
    const int row0 = blockIdx.x * GM;

    // --- A tile: load f32, convert bf16, padded smem ---
    {
        const float4* Z4 = (const float4*)(Z + (size_t)row0 * D);
        #pragma unroll
        for (int j = 0; j < 32; j++){
            int i = tid + 256 * j;        // 0..8191
            int r = i >> 6;               // row 0..127
            int f = i & 63;               // float4 idx -> k = f*4
            float4 v = Z4[r * 64 + f];
            __nv_bfloat162 p0 = __floats2bfloat162_rn(v.x, v.y);
            __nv_bfloat162 p1 = __floats2bfloat162_rn(v.z, v.w);
            uint2 pv; pv.x = *(unsigned*)&p0; pv.y = *(unsigned*)&p1;
            *(uint2*)(sa + r * A_STR + f * 4) = pv;
        }
    }
    #pragma unroll
    for (int j = 0; j < 4; j++) cn[tid + 256 * j] = g_cnorm[tid + 256 * j];
    if (tid < GM){ runmin[tid] = CUDART_INF_F; cnt[tid] = 0; }

    // --- B chunk loader: chunk index cc (0..31): ct = cc>>2, kc = cc&3 ---
    const __nv_bfloat16* cbsrc = g_cbf;
    auto issueB = [&](int cc){
        int ct = cc >> 2, kc = cc & 3;
        uint32_t dstb = sb_u + (uint32_t)((cc & 1) * 128 * B_STR * 2);
        #pragma unroll
        for (int j = 0; j < 4; j++){
            int i    = tid + 256 * j;     // 0..1023
            int code = i >> 3;            // 0..127
            int grp  = i & 7;             // 16B group
            uint32_t dst = dstb + (uint32_t)(code * B_STR * 2 + grp * 16);
            const void* src = cbsrc + (size_t)(ct * 128 + code) * D + kc * 64 + grp * 8;
            asm volatile("cp.async.cg.shared.global [%0], [%1], 16;"
                         :: "r"(dst), "l"(src) : "memory");
        }
        asm volatile("cp.async.commit_group;" ::: "memory");
    };

    issueB(0);
    __syncthreads();   // A + cn + init visible

    float acc[2][8][4];
    int   mycnt_dummy = 0; (void)mycnt_dummy;

    for (int cc = 0; cc < 32; cc++){
        const int kc = cc & 3;
        const int ct = cc >> 2;
        if (cc + 1 < 32) issueB(cc + 1);
        if (cc + 1 < 32) asm volatile("cp.async.wait_group 1;" ::: "memory");
        else             asm volatile("cp.async.wait_group 0;" ::: "memory");
        __syncthreads();                 // chunk cc visible to all

        if (kc == 0){
            #pragma unroll
            for (int m = 0; m < 2; m++)
                #pragma unroll
                for (int n = 0; n < 8; n++)
                    #pragma unroll
                    for (int q = 0; q < 4; q++) acc[m][n][q] = 0.f;
        }

        const __nv_bfloat16* sbc = sb + (cc & 1) * 128 * B_STR;
        #pragma unroll
        for (int ks = 0; ks < 4; ks++){
            int kb = kc * 64 + ks * 16;
            unsigned a[2][4];
            #pragma unroll
            for (int m = 0; m < 2; m++){
                int ra = wm * 32 + m * 16 + gid;
                const __nv_bfloat16* ap = sa + ra * A_STR + kb + 2 * tig;
                a[m][0] = *(const unsigned*)(ap);
                a[m][1] = *(const unsigned*)(ap + A_STR * 8);
                a[m][2] = *(const unsigned*)(ap + 8);
                a[m][3] = *(const unsigned*)(ap + A_STR * 8 + 8);
            }
            #pragma unroll
            for (int n = 0; n < 8; n++){
                int cbi = wn * 64 + n * 8 + gid;
                const __nv_bfloat16* bp = sbc + cbi * B_STR + ks * 16 + 2 * tig;
                unsigned b0 = *(const unsigned*)(bp);
                unsigned b1 = *(const unsigned*)(bp + 8);
                mma16816(acc[0][n], a[0], b0, b1);
                mma16816(acc[1][n], a[1], b0, b1);
            }
        }
        __syncthreads();                 // compute done before buf overwrite

        if (kc == 3){
            // ---- streaming epilogue for code tile ct (128 codes) ----
            // per-thread rows: wm*32 + m*16 + gid (+8); cols ct*128 + wn*64 + n*8 + 2*tig (+1)
            #pragma unroll
            for (int m = 0; m < 2; m++){
                int r0 = wm * 32 + m * 16 + gid;
                float mn0 = CUDART_INF_F, mn8 = CUDART_INF_F;
                #pragma unroll
                for (int n = 0; n < 8; n++){
                    int col = ct * 128 + wn * 64 + n * 8 + 2 * tig;
                    float c0 = cn[col], c1 = cn[col + 1];
                    mn0 = fminf(mn0, fminf(__fmaf_rn(-2.f, acc[m][n][0], c0),
                                           __fmaf_rn(-2.f, acc[m][n][1], c1)));
                    mn8 = fminf(mn8, fminf(__fmaf_rn(-2.f, acc[m][n][2], c0),
                                           __fmaf_rn(-2.f, acc[m][n][3], c1)));
                }
                // reduce over the 4 tig lanes (same gid)
                #pragma unroll
                for (int off = 1; off < 4; off <<= 1){
                    mn0 = fminf(mn0, __shfl_xor_sync(0xffffffffu, mn0, off));
                    mn8 = fminf(mn8, __shfl_xor_sync(0xffffffffu, mn8, off));
                }
                if (tig == 0){
                    tmin[r0 * 2 + wn]       = mn0;
                    tmin[(r0 + 8) * 2 + wn] = mn8;
                }
            }
            __syncthreads();
            if (tid < GM)
                runmin[tid] = fminf(runmin[tid],
                                    fminf(tmin[tid * 2], tmin[tid * 2 + 1]));
            __syncthreads();
            // ---- candidate emission (rare) ----
            #pragma unroll
            for (int m = 0; m < 2; m++){
                int r0 = wm * 32 + m * 16 + gid;
                float th0 = runmin[r0] + MARGIN;
                float th8 = runmin[r0 + 8] + MARGIN;
                #pragma unroll
                for (int n = 0; n < 8; n++){
                    int col = ct * 128 + wn * 64 + n * 8 + 2 * tig;
                    float c0 = cn[col], c1 = cn[col + 1];
                    float s0 = __fmaf_rn(-2.f, acc[m][n][0], c0);
                    float s1 = __fmaf_rn(-2.f, acc[m][n][1], c1);
                    float s2 = __fmaf_rn(-2.f, acc[m][n][2], c0);
                    float s3 = __fmaf_rn(-2.f, acc[m][n][3], c1);
                    if (s0 <= th0){
                        int p = atomicAdd(&cnt[r0], 1);
                        if (p < CAP) g_cand[(size_t)(row0 + r0) * CAP + p] = (unsigned short)col;
                    }
                    if (s1 <= th0){
                        int p = atomicAdd(&cnt[r0], 1);
                        if (p < CAP) g_cand[(size_t)(row0 + r0) * CAP + p] = (unsigned short)(col + 1);
                    }
                    if (s2 <= th8){
                        int p = atomicAdd(&cnt[r0 + 8], 1);
                        if (p < CAP) g_cand[(size_t)(row0 + r0 + 8) * CAP + p] = (unsigned short)col;
                    }
                    if (s3 <= th8){
                        int p = atomicAdd(&cnt[r0 + 8], 1);
                        if (p < CAP) g_cand[(size_t)(row0 + r0 + 8) * CAP + p] = (unsigned short)(col + 1);
                    }
                }
            }
            __syncthreads();
        }
    }
    if (tid < GM) g_ccnt[row0 + tid] = cnt[tid];
}

// ---------------------------------------------------------------------------
// Kernel 3: exact rescore (lanes = candidates) + fused gather/output/loss.
// 1 warp per row. Bit-exact round-0 arithmetic; lexicographic tie-break.
// ---------------------------------------------------------------------------
__global__ __launch_bounds__(256) void k_rescore(
    const float* __restrict__ Z, const float* __restrict__ CB,
    float4* __restrict__ Oz, float* __restrict__ out_idx)
{
    __shared__ float szs[8][256];
    __shared__ float wsum[8];
    const int w    = threadIdx.x >> 5;
    const int lane = threadIdx.x & 31;
    const int row  = blockIdx.x * 8 + w;
    float* zr = szs[w];
    const float4* zr4 = (const float4*)zr;

    const float4* Z4 = (const float4*)(Z + (size_t)row * D);
    #pragma unroll
    for (int j = 0; j < 2; j++)
        *(float4*)(zr + (lane + 32 * j) * 4) = Z4[lane + 32 * j];
    __syncwarp();

    // zn: exact 8-accumulator pairwise-halving tree (bit-match reference)
    int l8 = lane & 7;
    float a = 0.f;
    #pragma unroll
    for (int i = 0; i < 32; i++){
        float x = zr[i * 8 + l8];
        a = __fadd_rn(a, __fmul_rn(x, x));
    }
    float aj  = __shfl_sync(0xffffffffu, a, lane & 3);
    float aj4 = __shfl_sync(0xffffffffu, a, (lane & 3) + 4);
    float b   = __fadd_rn(aj, aj4);
    float b0 = __shfl_sync(0xffffffffu, b, 0);
    float b1 = __shfl_sync(0xffffffffu, b, 1);
    float b2 = __shfl_sync(0xffffffffu, b, 2);
    float b3 = __shfl_sync(0xffffffffu, b, 3);
    float zn = __fadd_rn(__fadd_rn(b0, b2), __fadd_rn(b1, b3));

    const int cnt = g_ccnt[row];
    float bs = CUDART_INF_F;
    int   bi = K;
    const float4* CB4 = (const float4*)CB;

    if (cnt <= CAP){
        if (lane < cnt){
            int ci = (int)g_cand[(size_t)row * CAP + lane];
            const float4* C4 = CB4 + (size_t)ci * 64;
            float dt = 0.f;
            #pragma unroll 16
            for (int q = 0; q < 64; q++){
                float4 cv = C4[q];
                float4 zv = zr4[q];
                dt = __fmaf_rn(zv.x, cv.x, dt);
                dt = __fmaf_rn(zv.y, cv.y, dt);
                dt = __fmaf_rn(zv.z, cv.z, dt);
                dt = __fmaf_rn(zv.w, cv.w, dt);
            }
            bs = __fmaf_rn(-2.0f, dt, __fadd_rn(zn, g_cnorm[ci]));
            bi = ci;
        }
    } else {
        // overflow fallback: full scan, 32 codes per lane
        for (int j = 0; j < 32; j++){
            int ci = j * 32 + lane;
            const float4* C4 = CB4 + (size_t)ci * 64;
            float dt = 0.f;
            #pragma unroll 16
            for (int q = 0; q < 64; q++){
                float4 cv = C4[q];
                float4 zv = zr4[q];
                dt = __fmaf_rn(zv.x, cv.x, dt);
                dt = __fmaf_rn(zv.y, cv.y, dt);
                dt = __fmaf_rn(zv.z, cv.z, dt);
                dt = __fmaf_rn(zv.w, cv.w, dt);
            }
            float s = __fmaf_rn(-2.0f, dt, __fadd_rn(zn, g_cnorm[ci]));
            if (s < bs || (s == bs && ci < bi)){ bs = s; bi = ci; }
        }
    }

    // lexicographic (score, index) min across warp
    #pragma unroll
    for (int off = 16; off; off >>= 1){
        float s2 = __shfl_xor_sync(0xffffffffu, bs, off);
        int   i2 = __shfl_xor_sync(0xffffffffu, bi, off);
        if (s2 < bs || (s2 == bs && i2 < bi)){ bs = s2; bi = i2; }
    }

    // fused gather: z_q_st output + loss partial
    const float4* C4b = CB4 + (size_t)bi * 64;
    float lsum = 0.f;
    #pragma unroll
    for (int q = 0; q < 2; q++){
        int j = lane + 32 * q;
        float4 z = zr4[j];
        float4 qv = C4b[j];
        float d0 = __fsub_rn(qv.x, z.x);
        float d1 = __fsub_rn(qv.y, z.y);
        float d2 = __fsub_rn(qv.z, z.z);
        float d3 = __fsub_rn(qv.w, z.w);
        float4 o;
        o.x = __fadd_rn(z.x, d0);
        o.y = __fadd_rn(z.y, d1);
        o.z = __fadd_rn(z.z, d2);
        o.w = __fadd_rn(z.w, d3);
        Oz[(size_t)row * 64 + j] = o;
        lsum += d0 * d0 + d1 * d1 + d2 * d2 + d3 * d3;
    }
    #pragma unroll
    for (int off = 16; off; off >>= 1)
        lsum += __shfl_xor_sync(0xffffffffu, lsum, off);
    if (lane == 0){
        wsum[w] = lsum;
        out_idx[row] = (float)bi;
    }
    __syncthreads();
    if (threadIdx.x == 0){
        float bsum = 0.f;
        #pragma unroll
        for (int i = 0; i < 8; i++) bsum += wsum[i];
        atomicAdd(&g_loss_sum, (double)bsum);
    }
}

// ---------------------------------------------------------------------------
__global__ void k_loss(float* __restrict__ out_loss, int n_total){
    double m  = g_loss_sum / (double)n_total;
    float  cb = (float)m;
    out_loss[0] = __fadd_rn(cb, __fmul_rn(0.25f, cb));
}

// ---------------------------------------------------------------------------
extern "C" void kernel_launch(void* const* d_in, const int* in_sizes, int n_in,
                              void* d_out, int out_size)
{
    const float* Z  = (const float*)d_in[0];
    const float* CB = (const float*)d_in[1];
    float* out = (float*)d_out;
    const int n_z = in_sizes[0];      // 16777216
    const int N   = n_z >> 8;         // 65536 rows

    k_setup<<<128, 256>>>(CB);

    const int gsmem = 110592;
    cudaFuncSetAttribute(k_gemm, cudaFuncAttributeMaxDynamicSharedMemorySize, gsmem);
    k_gemm<<<N / GM, 256, gsmem>>>(Z);

    // out layout: [ z_q_st (n_z) | vq_loss (1) | indices (N) ]
    k_rescore<<<N / 8, 256>>>(Z, CB, (float4*)out, out + n_z + 1);

    k_loss<<<1, 1>>>(out + n_z, n_z);
}

// round 10
// speedup vs baseline: 2.2050x; 1.0244x over previous
#include <cuda_runtime.h>
#include <cuda_bf16.h>
#include <cuda_fp16.h>
#include <math_constants.h>
#include <cstdint>

#define D      256
#define K      1024
#define NROWS  65536
#define GM     128          // rows per gemm block
#define CAP    16
#define MARGIN 3.0e-3f

__device__ float  g_cnorm[K];
__device__ double g_loss_sum;
__device__ __nv_bfloat16 g_cbf[K * D];       // bf16 codebook
__device__ unsigned short g_cand[NROWS * CAP];
__device__ int    g_ccnt[NROWS];

// ---------------------------------------------------------------------------
__device__ __forceinline__ void mma16816(float* c, const unsigned* a,
                                         unsigned b0, unsigned b1){
    asm volatile("mma.sync.aligned.m16n8k16.row.col.f32.bf16.bf16.f32 "
        "{%0,%1,%2,%3}, {%4,%5,%6,%7}, {%8,%9}, {%0,%1,%2,%3};"
        : "+f"(c[0]), "+f"(c[1]), "+f"(c[2]), "+f"(c[3])
        : "r"(a[0]), "r"(a[1]), "r"(a[2]), "r"(a[3]), "r"(b0), "r"(b1));
}

#define LDSM4(r, ad)                                                         \
    asm volatile("ldmatrix.sync.aligned.m8n8.x4.shared.b16 {%0,%1,%2,%3}, [%4];" \
        : "=r"((r)[0]), "=r"((r)[1]), "=r"((r)[2]), "=r"((r)[3]) : "r"(ad))

__device__ __forceinline__ uint32_t s2u(const void* p){
    uint32_t a;
    asm("{ .reg .u64 t; cvta.to.shared.u64 t, %1; cvt.u32.u64 %0, t; }" : "=r"(a) : "l"(p));
    return a;
}

// smem layout (bytes)
#define OFF_A   0          // 65536: A as [kb(4)][row(128)][128B], 16B-unit XOR swizzle
#define OFF_B   65536      // 32768: 2 bufs x [code(128)][128B], same swizzle
#define OFF_CN  98304      // 4096
#define OFF_CNT 102400     // 512
#define GSMEM   102912

// ---------------------------------------------------------------------------
// Kernel 1: codebook norms (bit-exact) + cb->bf16 + zero loss. grid 128 x 256.
// ---------------------------------------------------------------------------
__global__ void k_setup(const float* __restrict__ cb){
    if (blockIdx.x == 0 && threadIdx.x == 0) g_loss_sum = 0.0;
    int w    = threadIdx.x >> 5;
    int lane = threadIdx.x & 31;
    int code = blockIdx.x * 8 + w;
    const float* c = cb + (size_t)code * D;
    float s = 0.f;
    #pragma unroll
    for (int j = 0; j < 8; j++){
        float v = c[lane + 32 * j];
        s = __fmaf_rn(v, v, s);
    }
    #pragma unroll
    for (int off = 16; off; off >>= 1)
        s += __shfl_xor_sync(0xffffffffu, s, off);
    if (lane == 0) g_cnorm[code] = s;

    int g = blockIdx.x * 256 + threadIdx.x;
    const float4* cb4 = (const float4*)cb;
    float4 x = cb4[g * 2], y = cb4[g * 2 + 1];
    __nv_bfloat162 p0 = __floats2bfloat162_rn(x.x, x.y);
    __nv_bfloat162 p1 = __floats2bfloat162_rn(x.z, x.w);
    __nv_bfloat162 p2 = __floats2bfloat162_rn(y.x, y.y);
    __nv_bfloat162 p3 = __floats2bfloat162_rn(y.z, y.w);
    uint4 o;
    o.x = *(unsigned*)&p0; o.y = *(unsigned*)&p1;
    o.z = *(unsigned*)&p2; o.w = *(unsigned*)&p3;
    ((uint4*)g_cbf)[g] = o;
}

// ---------------------------------------------------------------------------
// Kernel 2: HMMA bf16 GEMM, warp tile 16 rows x 128 codes, ldmatrix fragments,
// single-barrier double-buffered k-chunks, register-resident running min,
// warp-local streaming candidate emission.
// ---------------------------------------------------------------------------
__global__ __launch_bounds__(256, 2) void k_gemm(const float* __restrict__ Z){
    extern __shared__ __align__(16) unsigned char smraw[];
    float* cn   = (float*)(smraw + OFF_CN);
    int*   scnt = (int*)(smraw + OFF_CNT);
    const uint32_t smem = s2u(smraw);

    const int tid  = threadIdx.x;
    const int l    = tid & 31;
    const int w    = tid >> 5;
    const int gid  = l >> 2;
    const int tig  = l & 3;
    const int row0 = blockIdx.x * GM;
    const int wr0  = w * 16;

    // --- A: load f32, convert bf16, store swizzled: [kb][row][unit^ (row&7)] ---
    {
        const float4* Z4 = (const float4*)(Z + (size_t)row0 * D);
        #pragma unroll
        for (int j = 0; j < 16; j++){
            int i = tid + 256 * j;          // 0..4095 : 16B units
            int r = i >> 5;                 // row 0..127
            int u = i & 31;                 // k-unit 0..31 (k = u*8)
            int kb = u >> 3, uu = u & 7;
            float4 v0 = Z4[r * 64 + u * 2];
            float4 v1 = Z4[r * 64 + u * 2 + 1];
            __nv_bfloat162 p0 = __floats2bfloat162_rn(v0.x, v0.y);
            __nv_bfloat162 p1 = __floats2bfloat162_rn(v0.z, v0.w);
            __nv_bfloat162 p2 = __floats2bfloat162_rn(v1.x, v1.y);
            __nv_bfloat162 p3 = __floats2bfloat162_rn(v1.z, v1.w);
            uint4 o;
            o.x = *(unsigned*)&p0; o.y = *(unsigned*)&p1;
            o.z = *(unsigned*)&p2; o.w = *(unsigned*)&p3;
            *(uint4*)(smraw + OFF_A + (kb * 128 + r) * 128
                      + ((uu ^ (r & 7)) << 4)) = o;
        }
    }
    #pragma unroll
    for (int j = 0; j < 4; j++) cn[tid + 256 * j] = g_cnorm[tid + 256 * j];
    if (tid < GM) scnt[tid] = 0;

    // --- B chunk loader (cc: ct = cc>>2 code tile, kc = cc&3 k-chunk) ---
    auto issueB = [&](int cc){
        int ct = cc >> 2, kc = cc & 3;
        uint32_t dstb = smem + OFF_B + (uint32_t)((cc & 1) << 14);
        #pragma unroll
        for (int j = 0; j < 4; j++){
            int i    = tid + 256 * j;       // 0..1023 16B units
            int code = i >> 3;
            int uu   = i & 7;
            uint32_t dst = dstb + (uint32_t)(code * 128 + ((uu ^ (code & 7)) << 4));
            const void* src = g_cbf + (size_t)(ct * 128 + code) * D + kc * 64 + uu * 8;
            asm volatile("cp.async.cg.shared.global [%0], [%1], 16;"
                         :: "r"(dst), "l"(src) : "memory");
        }
        asm volatile("cp.async.commit_group;" ::: "memory");
    };

    // --- ldmatrix per-thread address components ---
    const int arow  = wr0 + (l & 15);              // A row for this lane's addr
    const int asel  = l >> 4;                      // k-unit select
    const uint32_t abase = smem + OFF_A + (uint32_t)(arow * 128);
    const int ax = arow & 7;
    const int bno  = (l & 7) + ((l & 16) ? 8 : 0); // local code within n4 pair
    const int bsel = (l >> 3) & 1;
    const uint32_t bbase = smem + OFF_B + (uint32_t)(bno * 128);
    const int bx = bno & 7;

    issueB(0);

    float acc[16][4];
    float rm_lo = CUDART_INF_F, rm_hi = CUDART_INF_F;

    for (int cc = 0; cc < 32; cc++){
        const int kc = cc & 3;
        const int ct = cc >> 2;

        asm volatile("cp.async.wait_group 0;" ::: "memory");
        __syncthreads();                 // buf(cc) visible; buf(cc+1) free
        if (cc + 1 < 32) issueB(cc + 1);

        if (kc == 0){
            #pragma unroll
            for (int n = 0; n < 16; n++)
                #pragma unroll
                for (int q = 0; q < 4; q++) acc[n][q] = 0.f;
        }

        const uint32_t bufb = bbase + (uint32_t)((cc & 1) << 14);
        #pragma unroll
        for (int ks = 0; ks < 4; ks++){
            unsigned a[4];
            LDSM4(a, abase + (uint32_t)((kc << 14)
                   + ((((ks << 1) + asel) ^ ax) << 4)));
            #pragma unroll
            for (int n4 = 0; n4 < 8; n4++){
                unsigned b[4];
                LDSM4(b, bufb + (uint32_t)(n4 * 2048
                       + ((((ks << 1) + bsel) ^ bx) << 4)));
                mma16816(acc[2 * n4],     a, b[0], b[1]);
                mma16816(acc[2 * n4 + 1], a, b[2], b[3]);
            }
        }

        if (kc == 3){
            // ---- warp-local epilogue for code tile ct ----
            float mnlo = CUDART_INF_F, mnhi = CUDART_INF_F;
            #pragma unroll
            for (int n = 0; n < 16; n++){
                int col = ct * 128 + n * 8 + 2 * tig;
                float c0 = cn[col], c1 = cn[col + 1];
                mnlo = fminf(mnlo, fminf(__fmaf_rn(-2.f, acc[n][0], c0),
                                         __fmaf_rn(-2.f, acc[n][1], c1)));
                mnhi = fminf(mnhi, fminf(__fmaf_rn(-2.f, acc[n][2], c0),
                                         __fmaf_rn(-2.f, acc[n][3], c1)));
            }
            #pragma unroll
            for (int off = 1; off < 4; off <<= 1){
                mnlo = fminf(mnlo, __shfl_xor_sync(0xffffffffu, mnlo, off));
                mnhi = fminf(mnhi, __shfl_xor_sync(0xffffffffu, mnhi, off));
            }
            rm_lo = fminf(rm_lo, mnlo);
            rm_hi = fminf(rm_hi, mnhi);
            const float th_lo = rm_lo + MARGIN;
            const float th_hi = rm_hi + MARGIN;
            const int r_lo = wr0 + gid, r_hi = r_lo + 8;
            #pragma unroll
            for (int n = 0; n < 16; n++){
                int col = ct * 128 + n * 8 + 2 * tig;
                float c0 = cn[col], c1 = cn[col + 1];
                float s0 = __fmaf_rn(-2.f, acc[n][0], c0);
                float s1 = __fmaf_rn(-2.f, acc[n][1], c1);
                float s2 = __fmaf_rn(-2.f, acc[n][2], c0);
                float s3 = __fmaf_rn(-2.f, acc[n][3], c1);
                if (s0 <= th_lo){
                    int p = atomicAdd(&scnt[r_lo], 1);
                    if (p < CAP) g_cand[(size_t)(row0 + r_lo) * CAP + p] = (unsigned short)col;
                }
                if (s1 <= th_lo){
                    int p = atomicAdd(&scnt[r_lo], 1);
                    if (p < CAP) g_cand[(size_t)(row0 + r_lo) * CAP + p] = (unsigned short)(col + 1);
                }
                if (s2 <= th_hi){
                    int p = atomicAdd(&scnt[r_hi], 1);
                    if (p < CAP) g_cand[(size_t)(row0 + r_hi) * CAP + p] = (unsigned short)col;
                }
                if (s3 <= th_hi){
                    int p = atomicAdd(&scnt[r_hi], 1);
                    if (p < CAP) g_cand[(size_t)(row0 + r_hi) * CAP + p] = (unsigned short)(col + 1);
                }
            }
        }
    }
    __syncthreads();
    if (tid < GM) g_ccnt[row0 + tid] = scnt[tid];
}

// ---------------------------------------------------------------------------
// Kernel 3: exact rescore (lanes = candidates) + fused gather/output/loss.
// 1 warp per row. Bit-exact round-0 arithmetic; lexicographic tie-break.
// ---------------------------------------------------------------------------
__global__ __launch_bounds__(256) void k_rescore(
    const float* __restrict__ Z, const float* __restrict__ CB,
    float4* __restrict__ Oz, float* __restrict__ out_idx)
{
    __shared__ float szs[8][256];
    __shared__ float wsum[8];
    const int w    = threadIdx.x >> 5;
    const int lane = threadIdx.x & 31;
    const int row  = blockIdx.x * 8 + w;
    float* zr = szs[w];
    const float4* zr4 = (const float4*)zr;

    const float4* Z4 = (const float4*)(Z + (size_t)row * D);
    #pragma unroll
    for (int j = 0; j < 2; j++)
        *(float4*)(zr + (lane + 32 * j) * 4) = Z4[lane + 32 * j];
    __syncwarp();

    // zn: exact 8-accumulator pairwise-halving tree (bit-match reference)
    int l8 = lane & 7;
    float a = 0.f;
    #pragma unroll
    for (int i = 0; i < 32; i++){
        float x = zr[i * 8 + l8];
        a = __fadd_rn(a, __fmul_rn(x, x));
    }
    float aj  = __shfl_sync(0xffffffffu, a, lane & 3);
    float aj4 = __shfl_sync(0xffffffffu, a, (lane & 3) + 4);
    float b   = __fadd_rn(aj, aj4);
    float b0 = __shfl_sync(0xffffffffu, b, 0);
    float b1 = __shfl_sync(0xffffffffu, b, 1);
    float b2 = __shfl_sync(0xffffffffu, b, 2);
    float b3 = __shfl_sync(0xffffffffu, b, 3);
    float zn = __fadd_rn(__fadd_rn(b0, b2), __fadd_rn(b1, b3));

    const int cnt = g_ccnt[row];
    float bs = CUDART_INF_F;
    int   bi = K;
    const float4* CB4 = (const float4*)CB;

    if (cnt <= CAP){
        if (lane < cnt){
            int ci = (int)g_cand[(size_t)row * CAP + lane];
            const float4* C4 = CB4 + (size_t)ci * 64;
            float dt = 0.f;
            #pragma unroll 16
            for (int q = 0; q < 64; q++){
                float4 cv = C4[q];
                float4 zv = zr4[q];
                dt = __fmaf_rn(zv.x, cv.x, dt);
                dt = __fmaf_rn(zv.y, cv.y, dt);
                dt = __fmaf_rn(zv.z, cv.z, dt);
                dt = __fmaf_rn(zv.w, cv.w, dt);
            }
            bs = __fmaf_rn(-2.0f, dt, __fadd_rn(zn, g_cnorm[ci]));
            bi = ci;
        }
    } else {
        // overflow fallback: full scan, 32 codes per lane
        for (int j = 0; j < 32; j++){
            int ci = j * 32 + lane;
            const float4* C4 = CB4 + (size_t)ci * 64;
            float dt = 0.f;
            #pragma unroll 16
            for (int q = 0; q < 64; q++){
                float4 cv = C4[q];
                float4 zv = zr4[q];
                dt = __fmaf_rn(zv.x, cv.x, dt);
                dt = __fmaf_rn(zv.y, cv.y, dt);
                dt = __fmaf_rn(zv.z, cv.z, dt);
                dt = __fmaf_rn(zv.w, cv.w, dt);
            }
            float s = __fmaf_rn(-2.0f, dt, __fadd_rn(zn, g_cnorm[ci]));
            if (s < bs || (s == bs && ci < bi)){ bs = s; bi = ci; }
        }
    }

    // lexicographic (score, index) min across warp
    #pragma unroll
    for (int off = 16; off; off >>= 1){
        float s2 = __shfl_xor_sync(0xffffffffu, bs, off);
        int   i2 = __shfl_xor_sync(0xffffffffu, bi, off);
        if (s2 < bs || (s2 == bs && i2 < bi)){ bs = s2; bi = i2; }
    }

    // fused gather: z_q_st output + loss partial
    const float4* C4b = CB4 + (size_t)bi * 64;
    float lsum = 0.f;
    #pragma unroll
    for (int q = 0; q < 2; q++){
        int j = lane + 32 * q;
        float4 z = zr4[j];
        float4 qv = C4b[j];
        float d0 = __fsub_rn(qv.x, z.x);
        float d1 = __fsub_rn(qv.y, z.y);
        float d2 = __fsub_rn(qv.z, z.z);
        float d3 = __fsub_rn(qv.w, z.w);
        float4 o;
        o.x = __fadd_rn(z.x, d0);
        o.y = __fadd_rn(z.y, d1);
        o.z = __fadd_rn(z.z, d2);
        o.w = __fadd_rn(z.w, d3);
        Oz[(size_t)row * 64 + j] = o;
        lsum += d0 * d0 + d1 * d1 + d2 * d2 + d3 * d3;
    }
    #pragma unroll
    for (int off = 16; off; off >>= 1)
        lsum += __shfl_xor_sync(0xffffffffu, lsum, off);
    if (lane == 0){
        wsum[w] = lsum;
        out_idx[row] = (float)bi;
    }
    __syncthreads();
    if (threadIdx.x == 0){
        float bsum = 0.f;
        #pragma unroll
        for (int i = 0; i < 8; i++) bsum += wsum[i];
        atomicAdd(&g_loss_sum, (double)bsum);
    }
}

// ---------------------------------------------------------------------------
__global__ void k_loss(float* __restrict__ out_loss, int n_total){
    double m  = g_loss_sum / (double)n_total;
    float  cb = (float)m;
    out_loss[0] = __fadd_rn(cb, __fmul_rn(0.25f, cb));
}

// ---------------------------------------------------------------------------
extern "C" void kernel_launch(void* const* d_in, const int* in_sizes, int n_in,
                              void* d_out, int out_size)
{
    const float* Z  = (const float*)d_in[0];
    const float* CB = (const float*)d_in[1];
    float* out = (float*)d_out;
    const int n_z = in_sizes[0];      // 16777216
    const int N   = n_z >> 8;         // 65536 rows

    k_setup<<<128, 256>>>(CB);

    cudaFuncSetAttribute(k_gemm, cudaFuncAttributeMaxDynamicSharedMemorySize, GSMEM);
    k_gemm<<<N / GM, 256, GSMEM>>>(Z);

    // out layout: [ z_q_st (n_z) | vq_loss (1) | indices (N) ]
    k_rescore<<<N / 8, 256>>>(Z, CB, (float4*)out, out + n_z + 1);

    k_loss<<<1, 1>>>(out + n_z, n_z);
}